// round 1
// baseline (speedup 1.0000x reference)
#include <cuda_runtime.h>
#include <math.h>

#define N_NODES 500000
#define N_EDGES 32000000

// Scratch accumulators (allocation-free: __device__ globals)
__device__ float g_sum[N_NODES];
__device__ float g_cnt[N_NODES];

__global__ void zero_kernel() {
    int i = blockIdx.x * blockDim.x + threadIdx.x;
    if (i < N_NODES) {
        g_sum[i] = 0.0f;
        g_cnt[i] = 0.0f;
    }
}

__global__ void edge_kernel(const float* __restrict__ theta,
                            const int4* __restrict__ src4,
                            const int4* __restrict__ dst4,
                            const float* __restrict__ logc,
                            int nquads) {
    int i = blockIdx.x * blockDim.x + threadIdx.x;
    if (i >= nquads) return;
    float c = expf(*logc);

    int4 s = src4[i];
    int4 d = dst4[i];

    // Gather all 8 theta values up front (maximize MLP before atomics)
    float ts0 = __ldg(&theta[s.x]);
    float ts1 = __ldg(&theta[s.y]);
    float ts2 = __ldg(&theta[s.z]);
    float ts3 = __ldg(&theta[s.w]);
    float td0 = __ldg(&theta[d.x]);
    float td1 = __ldg(&theta[d.y]);
    float td2 = __ldg(&theta[d.z]);
    float td3 = __ldg(&theta[d.w]);

    float m0 = c * sinf(ts0 - td0);
    float m1 = c * sinf(ts1 - td1);
    float m2 = c * sinf(ts2 - td2);
    float m3 = c * sinf(ts3 - td3);

    atomicAdd(&g_sum[d.x], m0);
    atomicAdd(&g_sum[d.y], m1);
    atomicAdd(&g_sum[d.z], m2);
    atomicAdd(&g_sum[d.w], m3);
    atomicAdd(&g_cnt[d.x], 1.0f);
    atomicAdd(&g_cnt[d.y], 1.0f);
    atomicAdd(&g_cnt[d.z], 1.0f);
    atomicAdd(&g_cnt[d.w], 1.0f);
}

__global__ void node_kernel(const float* __restrict__ theta,
                            const float* __restrict__ u0p,
                            float* __restrict__ out) {
    int i = blockIdx.x * blockDim.x + threadIdx.x;
    if (i >= N_NODES) return;
    float u0 = *u0p;
    float s = g_sum[i];
    float cNt = g_cnt[i];
    float w = s / fmaxf(cNt, 1.0f);
    float t = theta[i];
    float sn, cs;
    sincosf(t, &sn, &cs);
    out[3 * i + 0] = w;
    out[3 * i + 1] = u0 * cs;
    out[3 * i + 2] = u0 * sn;
}

extern "C" void kernel_launch(void* const* d_in, const int* in_sizes, int n_in,
                              void* d_out, int out_size) {
    // Input order (setup_inputs): theta, logc, u0, src, dst
    const float* theta = (const float*)d_in[0];
    const float* logc  = (const float*)d_in[1];
    const float* u0    = (const float*)d_in[2];
    const int*   src   = (const int*)d_in[3];
    const int*   dst   = (const int*)d_in[4];
    float* out = (float*)d_out;

    const int nquads = N_EDGES / 4;  // 8M

    {
        int threads = 256;
        int blocks = (N_NODES + threads - 1) / threads;
        zero_kernel<<<blocks, threads>>>();
    }
    {
        int threads = 256;
        int blocks = (nquads + threads - 1) / threads;
        edge_kernel<<<blocks, threads>>>(theta, (const int4*)src, (const int4*)dst,
                                         logc, nquads);
    }
    {
        int threads = 256;
        int blocks = (N_NODES + threads - 1) / threads;
        node_kernel<<<blocks, threads>>>(theta, u0, out);
    }
}

// round 2
// speedup vs baseline: 1.8870x; 1.8870x over previous
#include <cuda_runtime.h>
#include <math.h>

#define N_NODES 500000
#define N_EDGES 32000000

// Accumulator per node: {sum sin(theta[src]), sum cos(theta[src]), count, pad}
__device__ float4 g_acc[N_NODES];
// Precomputed (sin(theta), cos(theta)) per node
__device__ float2 g_sc[N_NODES];

__device__ __forceinline__ void red_add_v4(float4* p, float a, float b, float c, float d) {
    asm volatile("red.global.add.v4.f32 [%0], {%1, %2, %3, %4};"
                 :: "l"(p), "f"(a), "f"(b), "f"(c), "f"(d) : "memory");
}

// Prologue: zero accumulators + precompute sin/cos of theta
__global__ void prologue_kernel(const float* __restrict__ theta) {
    int i = blockIdx.x * blockDim.x + threadIdx.x;
    if (i < N_NODES) {
        g_acc[i] = make_float4(0.0f, 0.0f, 0.0f, 0.0f);
        float sn, cs;
        sincosf(theta[i], &sn, &cs);
        g_sc[i] = make_float2(sn, cs);
    }
}

// Edge kernel: one gather + one vector atomic per edge. No trig.
__global__ void edge_kernel(const int4* __restrict__ src4,
                            const int4* __restrict__ dst4,
                            int nquads) {
    int i = blockIdx.x * blockDim.x + threadIdx.x;
    if (i >= nquads) return;

    int4 s = src4[i];
    int4 d = dst4[i];

    // Gather sin/cos at the 4 src nodes (4 independent 8B loads -> MLP)
    float2 sc0 = __ldg(&g_sc[s.x]);
    float2 sc1 = __ldg(&g_sc[s.y]);
    float2 sc2 = __ldg(&g_sc[s.z]);
    float2 sc3 = __ldg(&g_sc[s.w]);

    red_add_v4(&g_acc[d.x], sc0.x, sc0.y, 1.0f, 0.0f);
    red_add_v4(&g_acc[d.y], sc1.x, sc1.y, 1.0f, 0.0f);
    red_add_v4(&g_acc[d.z], sc2.x, sc2.y, 1.0f, 0.0f);
    red_add_v4(&g_acc[d.w], sc3.x, sc3.y, 1.0f, 0.0f);
}

// Epilogue: w = c * (cos(td)*Ssin - sin(td)*Scos) / max(cnt,1); v = u0*[cos,sin]
__global__ void node_kernel(const float* __restrict__ logc,
                            const float* __restrict__ u0p,
                            float* __restrict__ out) {
    int i = blockIdx.x * blockDim.x + threadIdx.x;
    if (i >= N_NODES) return;
    float c = expf(*logc);
    float u0 = *u0p;

    float4 acc = g_acc[i];           // {Ssin, Scos, cnt, _}
    float2 sc = g_sc[i];             // {sin(td), cos(td)}
    float w = c * (sc.y * acc.x - sc.x * acc.y) / fmaxf(acc.z, 1.0f);

    out[3 * i + 0] = w;
    out[3 * i + 1] = u0 * sc.y;
    out[3 * i + 2] = u0 * sc.x;
}

extern "C" void kernel_launch(void* const* d_in, const int* in_sizes, int n_in,
                              void* d_out, int out_size) {
    // Input order (setup_inputs): theta, logc, u0, src, dst
    const float* theta = (const float*)d_in[0];
    const float* logc  = (const float*)d_in[1];
    const float* u0    = (const float*)d_in[2];
    const int*   src   = (const int*)d_in[3];
    const int*   dst   = (const int*)d_in[4];
    float* out = (float*)d_out;

    const int nquads = N_EDGES / 4;  // 8M

    {
        int threads = 256;
        int blocks = (N_NODES + threads - 1) / threads;
        prologue_kernel<<<blocks, threads>>>(theta);
    }
    {
        int threads = 256;
        int blocks = (nquads + threads - 1) / threads;
        edge_kernel<<<blocks, threads>>>((const int4*)src, (const int4*)dst, nquads);
    }
    {
        int threads = 256;
        int blocks = (N_NODES + threads - 1) / threads;
        node_kernel<<<blocks, threads>>>(logc, u0, out);
    }
}